// round 13
// baseline (speedup 1.0000x reference)
#include <cuda_runtime.h>
#include <cuda_fp16.h>
#include <cstdint>

#define MT 8192
#define KD 4096
#define ND 4096

__device__ __half g_Wh[(size_t)ND * KD];   // NF4 levels (no absmax) [o][k]
__device__ __half g_Xh[(size_t)MT * KD];   // fp16 activations      [m][k]

__constant__ float c_nf4[16] = {
    -1.0f, -0.6961928009986877f, -0.5250730514526367f, -0.39491748809814453f,
    -0.28444138169288635f, -0.18477343022823334f, -0.09105003625154495f, 0.0f,
    0.07958029955625534f, 0.16093020141124725f, 0.24611230194568634f,
    0.33791524171829224f, 0.44070982933044434f, 0.5626170039176941f,
    0.7229568362236023f, 1.0f};

// ---------------------------------------------------------------------------
// Kernel 1: NF4 -> fp16 levels via warp-shfl LUT (absmax deferred to epilogue)
// ---------------------------------------------------------------------------
#define DQ_TOT (ND * (KD / 8))
#define DQ_S   (DQ_TOT / 4)

__global__ __launch_bounds__(256) void k_dequant(const int4* __restrict__ packed) {
    const int lane = threadIdx.x & 31;
    const uint32_t Lh = (uint32_t)__half_as_ushort(__float2half(c_nf4[lane & 15]));

    int t = blockIdx.x * blockDim.x + threadIdx.x;
    int4 p[4];
#pragma unroll
    for (int j = 0; j < 4; j++) p[j] = packed[t + j * DQ_S];
#pragma unroll
    for (int j = 0; j < 4; j++) {
        int v[4] = {p[j].x, p[j].y, p[j].z, p[j].w};
        uint32_t h[4];
#pragma unroll
        for (int q = 0; q < 4; q++) {
            int b = v[q] & 255;
            uint32_t hi = __shfl_sync(0xffffffffu, Lh, b >> 4);
            uint32_t lo = __shfl_sync(0xffffffffu, Lh, b & 15);
            h[q] = hi | (lo << 16);
        }
        *reinterpret_cast<int4*>(&g_Wh[(size_t)(t + j * DQ_S) * 8]) =
            *reinterpret_cast<int4*>(h);
    }
}

// ---------------------------------------------------------------------------
// Kernel 2: x f32 -> f16, MLP=8
// ---------------------------------------------------------------------------
#define CV_TOT (MT * (KD / 8))
#define CV_S   (CV_TOT / 4)

__global__ __launch_bounds__(256) void k_convert(const float4* __restrict__ x) {
    int t = blockIdx.x * blockDim.x + threadIdx.x;
    float4 a[4], b[4];
#pragma unroll
    for (int j = 0; j < 4; j++) {
        a[j] = x[(size_t)2 * (t + j * CV_S)];
        b[j] = x[(size_t)2 * (t + j * CV_S) + 1];
    }
#pragma unroll
    for (int j = 0; j < 4; j++) {
        __half2 h[4];
        h[0] = __float22half2_rn(make_float2(a[j].x, a[j].y));
        h[1] = __float22half2_rn(make_float2(a[j].z, a[j].w));
        h[2] = __float22half2_rn(make_float2(b[j].x, b[j].y));
        h[3] = __float22half2_rn(make_float2(b[j].z, b[j].w));
        *reinterpret_cast<int4*>(&g_Xh[(size_t)(t + j * CV_S) * 8]) =
            *reinterpret_cast<int4*>(h);
    }
}

// ---------------------------------------------------------------------------
// Kernel 3: HMMA GEMM.  BM=BN=128, BK=32, 4 warps, warp tile 64x64.
// 3-stage cp.async, wait_group 1, two barriers/iter.  3 CTAs/SM.
// Epilogue: out = absmax[n]*acc + bias[n].
// ---------------------------------------------------------------------------
#define BM 128
#define BN 128
#define BK 32
#define STG 3
#define PADK 40
#define A_STAGE (BM * PADK)
#define B_STAGE (BN * PADK)
#define SMEM_TOT ((STG * (A_STAGE + B_STAGE)) * 2)   // 61,440 bytes

static __device__ __forceinline__ uint32_t smem_u32(const void* p) {
    return (uint32_t)__cvta_generic_to_shared(p);
}

__global__ __launch_bounds__(128, 3) void k_gemm(const float* __restrict__ absmax,
                                                 const float* __restrict__ bias,
                                                 float* __restrict__ out) {
    extern __shared__ __align__(128) __half smem[];
    __half* As = smem;
    __half* Bs = smem + STG * A_STAGE;

    const int tid  = threadIdx.x;
    const int lane = tid & 31;
    const int warp = tid >> 5;
    const int wm   = warp >> 1;
    const int wn   = warp & 1;

    const int bn = blockIdx.x * BN;
    const int bm = blockIdx.y * BM;

    const __half* gA = g_Xh + (size_t)bm * KD;
    const __half* gB = g_Wh + (size_t)bn * KD;

    float acc[4][8][4];
#pragma unroll
    for (int mi = 0; mi < 4; mi++)
#pragma unroll
        for (int ni = 0; ni < 8; ni++)
#pragma unroll
            for (int j = 0; j < 4; j++) acc[mi][ni][j] = 0.0f;

    auto load_stage = [&](int s, int k0) {
        __half* as = As + s * A_STAGE;
        __half* bs = Bs + s * B_STAGE;
#pragma unroll
        for (int i = 0; i < 4; i++) {
            int c = i * 128 + tid;
            int row = c >> 2, col = (c & 3) * 8;
            asm volatile("cp.async.cg.shared.global [%0], [%1], 16;"
                         :: "r"(smem_u32(&as[row * PADK + col])),
                            "l"(gA + (size_t)row * KD + k0 + col));
            asm volatile("cp.async.cg.shared.global [%0], [%1], 16;"
                         :: "r"(smem_u32(&bs[row * PADK + col])),
                            "l"(gB + (size_t)row * KD + k0 + col));
        }
    };

    const int KT = KD / BK;                  // 128
#pragma unroll
    for (int s = 0; s < STG - 1; s++) {
        load_stage(s, s * BK);
        asm volatile("cp.async.commit_group;" ::: "memory");
    }

    const int a_row  = lane & 15;
    const int a_csel = (lane >> 4) * 8;
    const int b_row  = ((lane >> 4) & 1) * 8 + (lane & 7);
    const int b_csel = ((lane >> 3) & 1) * 8;

    int s_cur = 0, s_nxt = STG - 1;
    for (int kt = 0; kt < KT; kt++) {
        asm volatile("cp.async.wait_group %0;" :: "n"(STG - 2) : "memory");
        __syncthreads();

        if (kt + STG - 1 < KT) load_stage(s_nxt, (kt + STG - 1) * BK);
        asm volatile("cp.async.commit_group;" ::: "memory");

        const __half* as = As + s_cur * A_STAGE;
        const __half* bs = Bs + s_cur * B_STAGE;

#pragma unroll
        for (int ks = 0; ks < 2; ks++) {
            uint32_t af[4][4];
#pragma unroll
            for (int mi = 0; mi < 4; mi++) {
                uint32_t addr = smem_u32(&as[(wm * 64 + mi * 16 + a_row) * PADK + ks * 16 + a_csel]);
                asm volatile("ldmatrix.sync.aligned.m8n8.x4.shared.b16 {%0,%1,%2,%3}, [%4];"
                             : "=r"(af[mi][0]), "=r"(af[mi][1]), "=r"(af[mi][2]), "=r"(af[mi][3])
                             : "r"(addr));
            }
            uint32_t bf[4][4];
#pragma unroll
            for (int nb = 0; nb < 4; nb++) {
                uint32_t addr = smem_u32(&bs[(wn * 64 + nb * 16 + b_row) * PADK + ks * 16 + b_csel]);
                asm volatile("ldmatrix.sync.aligned.m8n8.x4.shared.b16 {%0,%1,%2,%3}, [%4];"
                             : "=r"(bf[nb][0]), "=r"(bf[nb][1]), "=r"(bf[nb][2]), "=r"(bf[nb][3])
                             : "r"(addr));
            }
#pragma unroll
            for (int mi = 0; mi < 4; mi++)
#pragma unroll
                for (int ni = 0; ni < 8; ni++) {
                    const int nb = ni >> 1;
                    const int hh = (ni & 1) * 2;
                    asm volatile(
                        "mma.sync.aligned.m16n8k16.row.col.f32.f16.f16.f32 "
                        "{%0,%1,%2,%3}, {%4,%5,%6,%7}, {%8,%9}, {%0,%1,%2,%3};"
                        : "+f"(acc[mi][ni][0]), "+f"(acc[mi][ni][1]),
                          "+f"(acc[mi][ni][2]), "+f"(acc[mi][ni][3])
                        : "r"(af[mi][0]), "r"(af[mi][1]), "r"(af[mi][2]), "r"(af[mi][3]),
                          "r"(bf[nb][hh]), "r"(bf[nb][hh + 1]));
                }
        }
        __syncthreads();   // lockstep barrier — removing this costs ~60% (R8)

        s_cur = (s_cur == STG - 1) ? 0 : s_cur + 1;
        s_nxt = (s_nxt == STG - 1) ? 0 : s_nxt + 1;
    }

    // Epilogue: out = absmax[n]*acc + bias[n]
    const int gr = lane >> 2;
    const int gc = (lane & 3) * 2;
#pragma unroll
    for (int mi = 0; mi < 4; mi++) {
#pragma unroll
        for (int ni = 0; ni < 8; ni++) {
            int m0 = bm + wm * 64 + mi * 16 + gr;
            int n0 = bn + wn * 64 + ni * 8 + gc;
            float2 am2 = *reinterpret_cast<const float2*>(&absmax[n0]);
            float2 bi2 = *reinterpret_cast<const float2*>(&bias[n0]);
            float2 v0 = make_float2(acc[mi][ni][0] * am2.x + bi2.x,
                                    acc[mi][ni][1] * am2.y + bi2.y);
            float2 v1 = make_float2(acc[mi][ni][2] * am2.x + bi2.x,
                                    acc[mi][ni][3] * am2.y + bi2.y);
            *reinterpret_cast<float2*>(&out[(size_t)m0 * ND + n0]) = v0;
            *reinterpret_cast<float2*>(&out[(size_t)(m0 + 8) * ND + n0]) = v1;
        }
    }
}

// ---------------------------------------------------------------------------
extern "C" void kernel_launch(void* const* d_in, const int* in_sizes, int n_in,
                              void* d_out, int out_size) {
    const float* x      = (const float*)d_in[0];
    const int*   packed = (const int*)d_in[1];
    const float* absmax = (const float*)d_in[2];
    const float* bias   = (const float*)d_in[3];
    float*       out    = (float*)d_out;

    cudaFuncSetAttribute(k_gemm, cudaFuncAttributeMaxDynamicSharedMemorySize, SMEM_TOT);

    k_dequant<<<DQ_S / 256, 256>>>((const int4*)packed);
    k_convert<<<CV_S / 256, 256>>>((const float4*)x);

    dim3 grid(ND / BN, MT / BM);   // (32, 64)
    k_gemm<<<grid, 128, SMEM_TOT>>>(absmax, bias, out);
}

// round 14
// speedup vs baseline: 1.0854x; 1.0854x over previous
#include <cuda_runtime.h>
#include <cuda_fp16.h>
#include <cstdint>

#define MT 8192
#define KD 4096
#define ND 4096

__device__ __half g_Wh[(size_t)ND * KD];   // NF4 levels (no absmax) [o][k]
__device__ __half g_Xh[(size_t)MT * KD];   // fp16 activations      [m][k]

__constant__ float c_nf4[16] = {
    -1.0f, -0.6961928009986877f, -0.5250730514526367f, -0.39491748809814453f,
    -0.28444138169288635f, -0.18477343022823334f, -0.09105003625154495f, 0.0f,
    0.07958029955625534f, 0.16093020141124725f, 0.24611230194568634f,
    0.33791524171829224f, 0.44070982933044434f, 0.5626170039176941f,
    0.7229568362236023f, 1.0f};

// ---------------------------------------------------------------------------
// Kernel 1: merged prepass.  bid%3==0 -> NF4 dequant block (2048 total),
// else -> f32->f16 convert block (4096 total).  Interleaved for concurrency.
// ---------------------------------------------------------------------------
#define DQ_TOT (ND * (KD / 8))     // 2,097,152 int4 units
#define DQ_S   (DQ_TOT / 4)        // 524,288 threads -> 2048 blocks of 256
#define CV_TOT (MT * (KD / 8))     // 4,194,304 pair units
#define CV_S   (CV_TOT / 4)        // 1,048,576 threads -> 4096 blocks of 256
#define PREP_GRID 6144

__global__ __launch_bounds__(256) void k_prep(const int4* __restrict__ packed,
                                              const float4* __restrict__ x) {
    const int bid = blockIdx.x;
    const int q   = bid / 3;
    const int r   = bid - q * 3;

    if (r == 0) {
        // ---- dequant block q (0..2047) ----
        const int lane = threadIdx.x & 31;
        const uint32_t Lh = (uint32_t)__half_as_ushort(__float2half(c_nf4[lane & 15]));
        int t = q * 256 + threadIdx.x;
        int4 p[4];
#pragma unroll
        for (int j = 0; j < 4; j++) p[j] = packed[t + j * DQ_S];
#pragma unroll
        for (int j = 0; j < 4; j++) {
            int v[4] = {p[j].x, p[j].y, p[j].z, p[j].w};
            uint32_t h[4];
#pragma unroll
            for (int qq = 0; qq < 4; qq++) {
                int b = v[qq] & 255;
                uint32_t hi = __shfl_sync(0xffffffffu, Lh, b >> 4);
                uint32_t lo = __shfl_sync(0xffffffffu, Lh, b & 15);
                h[qq] = hi | (lo << 16);
            }
            *reinterpret_cast<int4*>(&g_Wh[(size_t)(t + j * DQ_S) * 8]) =
                *reinterpret_cast<int4*>(h);
        }
    } else {
        // ---- convert block (q*2 + r-1) (0..4095) ----
        int cb = q * 2 + (r - 1);
        int t = cb * 256 + threadIdx.x;
        float4 a[4], b[4];
#pragma unroll
        for (int j = 0; j < 4; j++) {
            a[j] = x[(size_t)2 * (t + j * CV_S)];
            b[j] = x[(size_t)2 * (t + j * CV_S) + 1];
        }
#pragma unroll
        for (int j = 0; j < 4; j++) {
            __half2 h[4];
            h[0] = __float22half2_rn(make_float2(a[j].x, a[j].y));
            h[1] = __float22half2_rn(make_float2(a[j].z, a[j].w));
            h[2] = __float22half2_rn(make_float2(b[j].x, b[j].y));
            h[3] = __float22half2_rn(make_float2(b[j].z, b[j].w));
            *reinterpret_cast<int4*>(&g_Xh[(size_t)(t + j * CV_S) * 8]) =
                *reinterpret_cast<int4*>(h);
        }
    }
}

// ---------------------------------------------------------------------------
// Kernel 2: HMMA GEMM.  BM=BN=128, BK=32, 4 warps, warp tile 64x64.
// 4-stage cp.async, wait_group 2, two barriers/iter.  2 CTAs/SM.  (R10 config)
// Epilogue: out = absmax[n]*acc + bias[n].
// ---------------------------------------------------------------------------
#define BM 128
#define BN 128
#define BK 32
#define STG 4
#define PADK 40
#define A_STAGE (BM * PADK)
#define B_STAGE (BN * PADK)
#define SMEM_TOT ((STG * (A_STAGE + B_STAGE)) * 2)   // 81,920 bytes

static __device__ __forceinline__ uint32_t smem_u32(const void* p) {
    return (uint32_t)__cvta_generic_to_shared(p);
}

__global__ __launch_bounds__(128, 2) void k_gemm(const float* __restrict__ absmax,
                                                 const float* __restrict__ bias,
                                                 float* __restrict__ out) {
    extern __shared__ __align__(128) __half smem[];
    __half* As = smem;
    __half* Bs = smem + STG * A_STAGE;

    const int tid  = threadIdx.x;
    const int lane = tid & 31;
    const int warp = tid >> 5;
    const int wm   = warp >> 1;
    const int wn   = warp & 1;

    const int bn = blockIdx.x * BN;
    const int bm = blockIdx.y * BM;

    const __half* gA = g_Xh + (size_t)bm * KD;
    const __half* gB = g_Wh + (size_t)bn * KD;

    float acc[4][8][4];
#pragma unroll
    for (int mi = 0; mi < 4; mi++)
#pragma unroll
        for (int ni = 0; ni < 8; ni++)
#pragma unroll
            for (int j = 0; j < 4; j++) acc[mi][ni][j] = 0.0f;

    auto load_stage = [&](int s, int k0) {
        __half* as = As + s * A_STAGE;
        __half* bs = Bs + s * B_STAGE;
#pragma unroll
        for (int i = 0; i < 4; i++) {
            int c = i * 128 + tid;
            int row = c >> 2, col = (c & 3) * 8;
            asm volatile("cp.async.cg.shared.global [%0], [%1], 16;"
                         :: "r"(smem_u32(&as[row * PADK + col])),
                            "l"(gA + (size_t)row * KD + k0 + col));
            asm volatile("cp.async.cg.shared.global [%0], [%1], 16;"
                         :: "r"(smem_u32(&bs[row * PADK + col])),
                            "l"(gB + (size_t)row * KD + k0 + col));
        }
    };

    const int KT = KD / BK;                  // 128
#pragma unroll
    for (int s = 0; s < STG - 1; s++) {
        load_stage(s, s * BK);
        asm volatile("cp.async.commit_group;" ::: "memory");
    }

    const int a_row  = lane & 15;
    const int a_csel = (lane >> 4) * 8;
    const int b_row  = ((lane >> 4) & 1) * 8 + (lane & 7);
    const int b_csel = ((lane >> 3) & 1) * 8;

    for (int kt = 0; kt < KT; kt++) {
        asm volatile("cp.async.wait_group %0;" :: "n"(STG - 2) : "memory");
        __syncthreads();

        if (kt + STG - 1 < KT) load_stage((kt + STG - 1) & (STG - 1), (kt + STG - 1) * BK);
        asm volatile("cp.async.commit_group;" ::: "memory");

        const __half* as = As + (kt & (STG - 1)) * A_STAGE;
        const __half* bs = Bs + (kt & (STG - 1)) * B_STAGE;

#pragma unroll
        for (int ks = 0; ks < 2; ks++) {
            uint32_t af[4][4];
#pragma unroll
            for (int mi = 0; mi < 4; mi++) {
                uint32_t addr = smem_u32(&as[(wm * 64 + mi * 16 + a_row) * PADK + ks * 16 + a_csel]);
                asm volatile("ldmatrix.sync.aligned.m8n8.x4.shared.b16 {%0,%1,%2,%3}, [%4];"
                             : "=r"(af[mi][0]), "=r"(af[mi][1]), "=r"(af[mi][2]), "=r"(af[mi][3])
                             : "r"(addr));
            }
            uint32_t bf[4][4];
#pragma unroll
            for (int nb = 0; nb < 4; nb++) {
                uint32_t addr = smem_u32(&bs[(wn * 64 + nb * 16 + b_row) * PADK + ks * 16 + b_csel]);
                asm volatile("ldmatrix.sync.aligned.m8n8.x4.shared.b16 {%0,%1,%2,%3}, [%4];"
                             : "=r"(bf[nb][0]), "=r"(bf[nb][1]), "=r"(bf[nb][2]), "=r"(bf[nb][3])
                             : "r"(addr));
            }
#pragma unroll
            for (int mi = 0; mi < 4; mi++)
#pragma unroll
                for (int ni = 0; ni < 8; ni++) {
                    const int nb = ni >> 1;
                    const int hh = (ni & 1) * 2;
                    asm volatile(
                        "mma.sync.aligned.m16n8k16.row.col.f32.f16.f16.f32 "
                        "{%0,%1,%2,%3}, {%4,%5,%6,%7}, {%8,%9}, {%0,%1,%2,%3};"
                        : "+f"(acc[mi][ni][0]), "+f"(acc[mi][ni][1]),
                          "+f"(acc[mi][ni][2]), "+f"(acc[mi][ni][3])
                        : "r"(af[mi][0]), "r"(af[mi][1]), "r"(af[mi][2]), "r"(af[mi][3]),
                          "r"(bf[nb][hh]), "r"(bf[nb][hh + 1]));
                }
        }
        __syncthreads();   // lockstep barrier — removing this costs ~60% (R8)
    }

    // Epilogue: out = absmax[n]*acc + bias[n]
    const int gr = lane >> 2;
    const int gc = (lane & 3) * 2;
#pragma unroll
    for (int mi = 0; mi < 4; mi++) {
#pragma unroll
        for (int ni = 0; ni < 8; ni++) {
            int m0 = bm + wm * 64 + mi * 16 + gr;
            int n0 = bn + wn * 64 + ni * 8 + gc;
            float2 am2 = *reinterpret_cast<const float2*>(&absmax[n0]);
            float2 bi2 = *reinterpret_cast<const float2*>(&bias[n0]);
            float2 v0 = make_float2(acc[mi][ni][0] * am2.x + bi2.x,
                                    acc[mi][ni][1] * am2.y + bi2.y);
            float2 v1 = make_float2(acc[mi][ni][2] * am2.x + bi2.x,
                                    acc[mi][ni][3] * am2.y + bi2.y);
            *reinterpret_cast<float2*>(&out[(size_t)m0 * ND + n0]) = v0;
            *reinterpret_cast<float2*>(&out[(size_t)(m0 + 8) * ND + n0]) = v1;
        }
    }
}

// ---------------------------------------------------------------------------
extern "C" void kernel_launch(void* const* d_in, const int* in_sizes, int n_in,
                              void* d_out, int out_size) {
    const float* x      = (const float*)d_in[0];
    const int*   packed = (const int*)d_in[1];
    const float* absmax = (const float*)d_in[2];
    const float* bias   = (const float*)d_in[3];
    float*       out    = (float*)d_out;

    cudaFuncSetAttribute(k_gemm, cudaFuncAttributeMaxDynamicSharedMemorySize, SMEM_TOT);

    k_prep<<<PREP_GRID, 256>>>((const int4*)packed, (const float4*)x);

    dim3 grid(ND / BN, MT / BM);   // (32, 64)
    k_gemm<<<grid, 128, SMEM_TOT>>>(absmax, bias, out);
}